// round 15
// baseline (speedup 1.0000x reference)
#include <cuda_runtime.h>
#include <cuda_fp16.h>
#include <math.h>
#include <stdint.h>

#define BB 8
#define NSEQ 1024
#define CDIM 768
#define NH 12
#define HD 64
#define SCALE 0.125f
#define BNEPS 1e-5f
#define OUT_OFF (BB*NSEQ*CDIM)
#define NN ((size_t)NSEQ*NSEQ)

// plane sizes (hi plane at [0], lo plane at [OFF])
#define XOFF  (BB*NSEQ*CDIM)      // 6291456
#define WQOFF (3*CDIM*CDIM)       // 1769472
#define WPOFF (CDIM*CDIM)         // 589824
#define QOFF  (BB*NH*NSEQ*HD)     // 6291456
#define VOFF  (BB*NH*HD*NSEQ)     // 6291456
#define GOFF  (BB*NSEQ*CDIM)      // 6291456
#define MXOFF ((size_t)BB*NH*NSEQ*NSEQ)   // 100663296

// ---------------- scratch: merged hi/lo half planes ----------------------------
__device__ __half g_x  [2*XOFF];    // x * 16
__device__ __half g_wq [2*WQOFF];   // w_qkv * 1024
__device__ __half g_wp [2*WPOFF];   // w_proj * 1024
__device__ __half g_q  [2*QOFF];    // q * 32
__device__ __half g_k  [2*QOFF];    // k * 32
__device__ __half g_vts[2*VOFF];    // v^T * 32 [bh][d][m]
__device__ __half g_g  [2*GOFF];    // attn@v [b*N+n][c]
__device__ __half g_mx [2*MXOFF];   // raw mixed attn * 4096 [bh][n][m]
__device__ float  g_vt [VOFF];      // raw v^T
__device__ float  g_vc [BB*NH*HD];  // colsum of v per (bh, d)
__device__ float  g_logits[BB*NH*NSEQ*NSEQ];   // exp(SCALE*q.k)
__device__ float  g_rs[BB*NH*NSEQ];
__device__ double g_s1[NH];
__device__ double g_s2[NH];
__device__ float  g_bna[NH];
__device__ float  g_bnc[NH];

// ---------------- helpers -------------------------------------------------------
__device__ __forceinline__ uint32_t s2u(const void* p){
    uint32_t a;
    asm("{ .reg .u64 t; cvta.to.shared.u64 t, %1; cvt.u32.u64 %0, t; }" : "=r"(a) : "l"(p));
    return a;
}
__device__ __forceinline__ uint2 split2(float x0, float x1, float s){
    x0 *= s; x1 *= s;
    __half h0 = __float2half_rn(x0), h1 = __float2half_rn(x1);
    __half g0 = __float2half_rn(x0 - __half2float(h0));
    __half g1 = __float2half_rn(x1 - __half2float(h1));
    __half2 hh = __halves2half2(h0, h1), ll = __halves2half2(g0, g1);
    uint2 r;
    r.x = *(uint32_t*)&hh; r.y = *(uint32_t*)&ll;
    return r;
}
__device__ __forceinline__ void mma16f(float* c, const uint32_t* a, const uint32_t* b){
    asm volatile("mma.sync.aligned.m16n8k16.row.col.f32.f16.f16.f32 "
        "{%0,%1,%2,%3}, {%4,%5,%6,%7}, {%8,%9}, {%0,%1,%2,%3};"
        : "+f"(c[0]), "+f"(c[1]), "+f"(c[2]), "+f"(c[3])
        : "r"(a[0]), "r"(a[1]), "r"(a[2]), "r"(a[3]), "r"(b[0]), "r"(b[1]));
}
__device__ __forceinline__ void mma16h(uint32_t* c, const uint32_t* a, const uint32_t* b){
    asm volatile("mma.sync.aligned.m16n8k16.row.col.f16.f16.f16.f16 "
        "{%0,%1}, {%2,%3,%4,%5}, {%6,%7}, {%0,%1};"
        : "+r"(c[0]), "+r"(c[1])
        : "r"(a[0]), "r"(a[1]), "r"(a[2]), "r"(a[3]), "r"(b[0]), "r"(b[1]));
}
__device__ __forceinline__ void ldsm4(uint32_t& r0, uint32_t& r1, uint32_t& r2,
                                      uint32_t& r3, uint32_t addr){
    asm volatile("ldmatrix.sync.aligned.m8n8.x4.shared.b16 {%0,%1,%2,%3}, [%4];"
        : "=r"(r0), "=r"(r1), "=r"(r2), "=r"(r3) : "r"(addr));
}
__device__ __forceinline__ void cpa16(uint32_t dst, const void* src){
    asm volatile("cp.async.cg.shared.global [%0], [%1], 16;" :: "r"(dst), "l"(src));
}
#define CPA_COMMIT() asm volatile("cp.async.commit_group;" ::: "memory")
#define USWZ(row, kg) ((row)*64 + (((kg) ^ (((row)>>1)&3)) << 4))

// ---------------- init ----------------------------------------------------------
__global__ void k_init(){
    int i = blockIdx.x * blockDim.x + threadIdx.x;
    if (i < BB*NH*NSEQ) g_rs[i] = 0.f;
    if (i < BB*NH*HD)   g_vc[i] = 0.f;
    if (i < NH) { g_s1[i] = 0.0; g_s2[i] = 0.0; }
}

// ---------------- pre-split: fp32 -> hi/lo half planes ---------------------------
__global__ void k_split(const float* __restrict__ src, int n8, float s, int sel){
    int i = blockIdx.x * blockDim.x + threadIdx.x;
    if (i >= n8) return;
    const float* p = (sel == 3) ? g_vt : src;
    float4 a = *(const float4*)(p + 8*(size_t)i);
    float4 b = *(const float4*)(p + 8*(size_t)i + 4);
    uint2 u0 = split2(a.x, a.y, s), u1 = split2(a.z, a.w, s);
    uint2 u2 = split2(b.x, b.y, s), u3 = split2(b.z, b.w, s);
    __half* dh; size_t off;
    if (sel == 0)      { dh = g_x;   off = XOFF; }
    else if (sel == 1) { dh = g_wq;  off = WQOFF; }
    else if (sel == 2) { dh = g_wp;  off = WPOFF; }
    else               { dh = g_vts; off = VOFF; }
    uint4 vh = {u0.x, u1.x, u2.x, u3.x};
    uint4 vl = {u0.y, u1.y, u2.y, u3.y};
    *(uint4*)(dh + 8*(size_t)i)       = vh;
    *(uint4*)(dh + off + 8*(size_t)i) = vl;
    if (sel == 3) {
        float cs = (a.x+a.y+a.z+a.w) + (b.x+b.y+b.z+b.w);
        atomicAdd(&g_vc[(8*(size_t)i) >> 10], cs);
    }
}

// ---------------- ldmatrix MMA core: one k32 chunk -------------------------------
template<int NT, int MT>
__device__ __forceinline__ void mma_chunk_p(
    uint32_t ah_b, uint32_t alo, uint32_t bh_b, uint32_t blo,
    const int* rba, const int* swa, int kha,
    const int* rbb, const int* swb, int khb,
    float accf[MT][NT][4], uint32_t acch[MT][NT][2])
{
    #pragma unroll
    for (int ks = 0; ks < 2; ks++) {
        uint32_t ah[MT][4], al[MT][4], bh4[NT/2][4], bl4[NT/2][4];
        #pragma unroll
        for (int i = 0; i < MT; i++) {
            int kg = ks*2 + kha;
            uint32_t off = rba[i] + (((uint32_t)(kg ^ swa[i])) << 4);
            ldsm4(ah[i][0], ah[i][1], ah[i][2], ah[i][3], ah_b + off);
            ldsm4(al[i][0], al[i][1], al[i][2], al[i][3], ah_b + alo + off);
        }
        #pragma unroll
        for (int g = 0; g < NT/2; g++) {
            int kg = ks*2 + khb;
            uint32_t off = rbb[g] + (((uint32_t)(kg ^ swb[g])) << 4);
            ldsm4(bh4[g][0], bh4[g][1], bh4[g][2], bh4[g][3], bh_b + off);
            ldsm4(bl4[g][0], bl4[g][1], bl4[g][2], bl4[g][3], bh_b + blo + off);
        }
        #pragma unroll
        for (int g = 0; g < NT/2; g++) {
            #pragma unroll
            for (int jj = 0; jj < 2; jj++) {
                int j = g*2 + jj;
                uint32_t bh2[2] = {bh4[g][jj*2], bh4[g][jj*2+1]};
                uint32_t bl2[2] = {bl4[g][jj*2], bl4[g][jj*2+1]};
                #pragma unroll
                for (int i = 0; i < MT; i++) {
                    mma16f(accf[i][j], ah[i], bh2);
                    mma16h(acch[i][j], al[i], bh2);
                    mma16h(acch[i][j], ah[i], bl2);
                }
            }
        }
    }
}

// ---------------- fp16x3 GEMM ----------------------------------------------------
// MODE 0: qkv  A=g_x   B=g_wq  K=768  BM=64 pipelined -> q,k planes + raw v^T
// MODE 1: qk   A=g_q   B=g_k   K=64   BM=128 SINGLE-SHOT -> exp + row-sum atomics
// MODE 2: av   A=g_mx  B=g_vts K=1024 BM=64 pipelined -> g_g + FUSED attn -> d_out
// MODE 3: proj A=g_g   B=g_wp  K=768  BM=64 pipelined -> d_out (+bias)
template<int MODE>
__global__ __launch_bounds__(256, 3) void gemm_h(
    const float* __restrict__ bias, float* __restrict__ pC)
{
    constexpr int BM = (MODE==1) ? 128 : 64;
    constexpr int BN = 64;
    constexpr int NT = 4, MT = BM / 64;
    constexpr int K   = (MODE==1) ? 64 : (MODE==2) ? 1024 : 768;
    constexpr int NC  = K / 32;
    constexpr int APL = BM * 64;            // bytes per A plane
    constexpr int BPL = BN * 64;            // bytes per B plane
    constexpr int STG = 2*APL + 2*BPL;      // stage size

    extern __shared__ __align__(16) char smem[];

    const int tid  = threadIdx.x;
    const int lane = tid & 31, warp = tid >> 5;
    const int wm = warp >> 1, wn = warp & 1;
    const int gid = lane >> 2, tig = lane & 3;
    const int Mblk = blockIdx.y * BM;
    const int Nblk = blockIdx.x * BN;
    const int bh   = blockIdx.z;
    const uint32_t sb = s2u(smem);

    // per-lane ldmatrix address components
    int rba[MT], swa[MT], rbb[NT/2], swb[NT/2];
    const int rA  = (lane & 7) + ((lane & 8) ? 8 : 0);
    const int kha = (lane >> 4) & 1;
    #pragma unroll
    for (int i = 0; i < MT; i++) {
        int row = wm*(MT*16) + i*16 + rA;
        rba[i] = row*64; swa[i] = (row>>1)&3;
    }
    const int rB  = (lane & 7) + ((lane & 16) ? 8 : 0);
    const int khb = (lane >> 3) & 1;
    #pragma unroll
    for (int g = 0; g < NT/2; g++) {
        int row = wn*32 + g*16 + rB;
        rbb[g] = row*64; swb[g] = (row>>1)&3;
    }

    const __half *Ah_g, *Bh_g;
    constexpr size_t ALO = (MODE==0) ? XOFF : (MODE==1) ? QOFF :
                           (MODE==2) ? MXOFF : GOFF;
    constexpr size_t BLO = (MODE==0) ? WQOFF : (MODE==1) ? QOFF :
                           (MODE==2) ? VOFF : WPOFF;
    if constexpr (MODE == 0)      { Ah_g = g_x; Bh_g = g_wq; }
    else if constexpr (MODE == 1) { size_t o = (size_t)bh*NSEQ*HD;
                                    Ah_g = g_q + o; Bh_g = g_k + o; }
    else if constexpr (MODE == 2) { Ah_g = g_mx + (size_t)bh*NN;
                                    Bh_g = g_vts + (size_t)bh*HD*NSEQ; }
    else                          { Ah_g = g_g; Bh_g = g_wp; }

    // BN affine constants (MODE 2 only)
    float na = 0.f, ncs = 0.f, an = 0.f;
    if constexpr (MODE == 2) {
        int gg = bh % NH;
        na = g_bna[gg]; ncs = g_bnc[gg];
        an = na * (1.f / 4096.f);
    }

    float accf[MT][NT][4] = {};
    uint32_t acch[MT][NT][2] = {};

    {
        const int r0 = tid >> 2, kg = tid & 3;
        auto issue = [&](int ch, int s) {
            uint32_t base = sb + s*STG;
            #pragma unroll
            for (int i = 0; i < BM/64; i++) {
                int r = r0 + i*64;
                uint32_t d = base + USWZ(r, kg);
                const __half* src = Ah_g + (size_t)(Mblk + r)*K + ch*32 + kg*8;
                cpa16(d,       src);
                cpa16(d + APL, src + ALO);
            }
            {
                uint32_t d = base + 2*APL + USWZ(r0, kg);
                const __half* src = Bh_g + (size_t)(Nblk + r0)*K + ch*32 + kg*8;
                cpa16(d,       src);
                cpa16(d + BPL, src + BLO);
            }
            CPA_COMMIT();
        };
        if constexpr (MODE == 1) {
            // ======== single-shot: both K-chunks resident, one barrier ========
            issue(0, 0);
            issue(1, 1);
            asm volatile("cp.async.wait_group 0;" ::: "memory");
            __syncthreads();
            mma_chunk_p<NT, MT>(sb,       APL, sb + 2*APL,       BPL,
                                rba, swa, kha, rbb, swb, khb, accf, acch);
            mma_chunk_p<NT, MT>(sb + STG, APL, sb + STG + 2*APL, BPL,
                                rba, swa, kha, rbb, swb, khb, accf, acch);
        } else {
            // ======== 3-stage cp.async pipeline, one barrier per chunk ========
            issue(0, 0);
            issue(1, 1);
            int s_cur = 0, s_nxt2 = 2;
            for (int ch = 0; ch < NC; ch++) {
                if (ch < NC - 1) {
                    asm volatile("cp.async.wait_group 1;" ::: "memory");
                } else {
                    asm volatile("cp.async.wait_group 0;" ::: "memory");
                }
                __syncthreads();
                if (ch + 2 < NC) issue(ch + 2, s_nxt2);
                uint32_t base = sb + s_cur*STG;
                if constexpr (MODE == 2) {
                    // FUSED attn output: read staged A tile (hi+lo), apply
                    // bna/4096*(hi+lo)+bnc, stream to d_out attn slot.
                    const int rr = tid >> 2;
                    const int kp = tid & 3;
                    uint32_t o0 = base + USWZ(rr, kp);
                    uint4 hv = *(const uint4*)(smem + (o0 - sb));
                    uint4 lv = *(const uint4*)(smem + (o0 - sb) + APL);
                    float* dst = pC + OUT_OFF + (size_t)bh*NN
                               + (size_t)(Mblk + rr)*1024 + ch*32 + kp*8;
                    const uint32_t hw[4] = {hv.x, hv.y, hv.z, hv.w};
                    const uint32_t lw[4] = {lv.x, lv.y, lv.z, lv.w};
                    #pragma unroll
                    for (int q = 0; q < 2; q++) {
                        float4 r;
                        float2 a0 = __half22float2(*(__half2*)&hw[q*2+0]);
                        float2 b0 = __half22float2(*(__half2*)&lw[q*2+0]);
                        float2 a1 = __half22float2(*(__half2*)&hw[q*2+1]);
                        float2 b1 = __half22float2(*(__half2*)&lw[q*2+1]);
                        r.x = fmaf(an, a0.x + b0.x, ncs);
                        r.y = fmaf(an, a0.y + b0.y, ncs);
                        r.z = fmaf(an, a1.x + b1.x, ncs);
                        r.w = fmaf(an, a1.y + b1.y, ncs);
                        __stcs((float4*)(dst + q*4), r);
                    }
                }
                mma_chunk_p<NT, MT>(base, APL, base + 2*APL, BPL,
                                    rba, swa, kha, rbb, swb, khb, accf, acch);
                s_cur = (s_cur == 2) ? 0 : s_cur + 1;
                s_nxt2 = (s_nxt2 == 2) ? 0 : s_nxt2 + 1;
            }
            __syncthreads();
        }
    }

    // ----------------- epilogue -----------------
    // UN: qkv 2^-14 (16*1024); qk 2^-10 (32*32); av 2^-17 (4096*32); proj 2^-10
    constexpr float UN = (MODE==0) ? (1.f/16384.f) : (MODE==2) ? (1.f/131072.f)
                                                               : (1.f/1024.f);
    if constexpr (MODE == 1) {
        #pragma unroll
        for (int i = 0; i < MT; i++) {
            #pragma unroll
            for (int p = 0; p < 2; p++) {
                const int row = Mblk + wm*(MT*16) + i*16 + gid + p*8;
                float rsum = 0.f;
                #pragma unroll
                for (int j = 0; j < NT; j++) {
                    __half2 q = *(__half2*)&acch[i][j][p];
                    float2 cc = __half22float2(q);
                    float v0 = (accf[i][j][p*2+0] + cc.x) * UN;
                    float v1 = (accf[i][j][p*2+1] + cc.y) * UN;
                    float e0 = __expf(SCALE * v0);
                    float e1 = __expf(SCALE * v1);
                    int c0 = Nblk + wn*32 + j*8 + tig*2;
                    __stcs((float2*)(g_logits + (size_t)bh*NN + (size_t)row*NSEQ + c0),
                           make_float2(e0, e1));
                    rsum += e0 + e1;
                }
                rsum += __shfl_xor_sync(0xffffffffu, rsum, 1);
                rsum += __shfl_xor_sync(0xffffffffu, rsum, 2);
                if (tig == 0)
                    atomicAdd(&g_rs[(size_t)bh*NSEQ + row], rsum);
            }
        }
    } else {
        #pragma unroll
        for (int i = 0; i < MT; i++) {
            #pragma unroll
            for (int j = 0; j < NT; j++) {
                __half2 q0 = *(__half2*)&acch[i][j][0];
                __half2 q1 = *(__half2*)&acch[i][j][1];
                float2 c01 = __half22float2(q0);
                float2 c23 = __half22float2(q1);
                float cv[4] = {accf[i][j][0] + c01.x, accf[i][j][1] + c01.y,
                               accf[i][j][2] + c23.x, accf[i][j][3] + c23.y};
                int r0 = Mblk + wm*(MT*16) + i*16 + gid;
                int c0 = Nblk + wn*32 + j*8 + tig*2;
                #pragma unroll
                for (int p = 0; p < 2; p++) {
                    int row = r0 + p*8;
                    float v0 = cv[p*2+0] * UN, v1 = cv[p*2+1] * UN;
                    if constexpr (MODE == 0) {
                        int t3 = c0 / CDIM; int rem = c0 - t3*CDIM;
                        int h = rem >> 6, d = rem & 63;
                        int b = row >> 10, n = row & (NSEQ - 1);
                        v0 += bias[c0]; v1 += bias[c0+1];
                        if (t3 < 2) {
                            uint2 sp = split2(v0, v1, 32.f);
                            size_t idx = ((((size_t)(b*NH+h))*NSEQ + n) << 6) + d;
                            __half* dst = (t3 == 0) ? g_q : g_k;
                            *(uint32_t*)(dst + idx)        = sp.x;
                            *(uint32_t*)(dst + QOFF + idx) = sp.y;
                        } else {
                            size_t base = (((size_t)(b*NH+h))*HD + d)*NSEQ + n;
                            g_vt[base]        = v0;
                            g_vt[base + NSEQ] = v1;
                        }
                    } else if constexpr (MODE == 2) {
                        // out = bna*(mix@v) + bnc*colsum(v)
                        int b = bh / NH, g = bh % NH;
                        float w0 = fmaf(na, v0, ncs * g_vc[bh*HD + c0]);
                        float w1 = fmaf(na, v1, ncs * g_vc[bh*HD + c0 + 1]);
                        uint2 sp = split2(w0, w1, 1.f);
                        size_t idx = ((size_t)(b*NSEQ + row))*CDIM + g*HD + c0;
                        *(uint32_t*)(g_g + idx)        = sp.x;
                        *(uint32_t*)(g_g + GOFF + idx) = sp.y;
                    } else {
                        float2 s = make_float2(v0 + bias[c0], v1 + bias[c0+1]);
                        *(float2*)(pC + (size_t)row*CDIM + c0) = s;
                    }
                }
            }
        }
    }
}

// ---------------- streaming softmax-finish + head mix + BN stats ---------------
// writes raw mixed attn as SPLIT fp16 planes (x4096) into g_mx
__global__ void k_mix(const float* __restrict__ w_re, const float* __restrict__ b_re) {
    __shared__ float wre[NH][NH];
    __shared__ float bre[NH], sinv[NH];
    __shared__ float sm1[NH], sm2[NH];
    const int b = blockIdx.x >> 10;
    const int n = blockIdx.x & 1023;
    const int t = threadIdx.x;               // 256
    const int lane = t & 31;
    if (t < NH*NH) wre[t/NH][t%NH] = w_re[t];
    if (t < NH) {
        bre[t] = b_re[t];
        sinv[t] = 1.0f / g_rs[((size_t)(b*NH + t))*NSEQ + n];
        sm1[t] = 0.f; sm2[t] = 0.f;
    }
    __syncthreads();
    const int m = t << 2;
    float L[NH][4];
    #pragma unroll
    for (int h = 0; h < NH; h++) {
        float4 e = __ldcs((const float4*)(g_logits +
                      (((size_t)(b*NH+h))*NSEQ + n)*NSEQ + m));
        float si = sinv[h];
        L[h][0] = e.x*si; L[h][1] = e.y*si; L[h][2] = e.z*si; L[h][3] = e.w*si;
    }
    #pragma unroll
    for (int g = 0; g < NH; g++) {
        float o0=bre[g], o1=bre[g], o2=bre[g], o3=bre[g];
        #pragma unroll
        for (int h = 0; h < NH; h++) {
            float w = wre[g][h];
            o0 = fmaf(w, L[h][0], o0); o1 = fmaf(w, L[h][1], o1);
            o2 = fmaf(w, L[h][2], o2); o3 = fmaf(w, L[h][3], o3);
        }
        size_t idx = (((size_t)(b*NH+g))*NSEQ + n)*NSEQ + m;
        uint2 u01 = split2(o0, o1, 4096.f);
        uint2 u23 = split2(o2, o3, 4096.f);
        uint2 sh = {u01.x, u23.x};
        uint2 sl = {u01.y, u23.y};
        __stcs((uint2*)(g_mx + idx), sh);
        __stcs((uint2*)(g_mx + MXOFF + idx), sl);
        float a = (o0+o1)+(o2+o3);
        float c = o0*o0+o1*o1+o2*o2+o3*o3;
        #pragma unroll
        for (int o = 16; o; o >>= 1) {
            a += __shfl_xor_sync(0xffffffffu, a, o);
            c += __shfl_xor_sync(0xffffffffu, c, o);
        }
        if (lane == 0) { atomicAdd(&sm1[g], a); atomicAdd(&sm2[g], c); }
    }
    __syncthreads();
    if (t < NH) {
        atomicAdd(&g_s1[t], (double)sm1[t]);
        atomicAdd(&g_s2[t], (double)sm2[t]);
    }
}

// ---------------- BN finalize (double precision) --------------------------------
__global__ void k_bnfin(const float* __restrict__ gamma, const float* __restrict__ beta) {
    int g = threadIdx.x;
    if (g < NH) {
        double cnt = (double)BB * NSEQ * NSEQ;
        double mean = g_s1[g] / cnt;
        double var  = g_s2[g] / cnt - mean * mean;
        float a = (float)((double)gamma[g] / sqrt(var + (double)BNEPS));
        g_bna[g] = a;
        g_bnc[g] = beta[g] - a * (float)mean;
    }
}

// ---------------- launcher --------------------------------------------------------
extern "C" void kernel_launch(void* const* d_in, const int* in_sizes, int n_in,
                              void* d_out, int out_size) {
    const float* x    = (const float*)d_in[0];
    const float* wqkv = (const float*)d_in[1];
    const float* bqkv = (const float*)d_in[2];
    const float* wre  = (const float*)d_in[3];
    const float* bre  = (const float*)d_in[4];
    const float* gam  = (const float*)d_in[5];
    const float* bet  = (const float*)d_in[6];
    const float* wp   = (const float*)d_in[7];
    const float* bp   = (const float*)d_in[8];
    float* out = (float*)d_out;

    const int SM0 = 3 * 16384;   // 49152 (mode 0: BM=64, 3-stage)
    const int SM1 = 2 * 24576;   // 49152 (mode 1: BM=128, single-shot 2 stages)
    const int SM2 = 3 * 16384;   // 49152 (mode 2: BM=64, 3-stage)
    const int SM3 = 3 * 16384;   // 49152 (mode 3: BM=64, 3-stage)
    cudaFuncSetAttribute(gemm_h<0>, cudaFuncAttributeMaxDynamicSharedMemorySize, SM0);
    cudaFuncSetAttribute(gemm_h<1>, cudaFuncAttributeMaxDynamicSharedMemorySize, SM1);
    cudaFuncSetAttribute(gemm_h<2>, cudaFuncAttributeMaxDynamicSharedMemorySize, SM2);
    cudaFuncSetAttribute(gemm_h<3>, cudaFuncAttributeMaxDynamicSharedMemorySize, SM3);

    k_init<<<96, 1024>>>();                                           // 1
    k_split<<<3072, 256>>>(x,    786432, 16.f,   0);                  // 2: x
    k_split<<<864,  256>>>(wqkv, 221184, 1024.f, 1);                  // 3: w_qkv
    gemm_h<0><<<dim3(36, 128, 1), 256, SM0>>>(bqkv, nullptr);         // 4: qkv (PROFILED)
    k_split<<<288,  256>>>(wp,    73728, 1024.f, 2);                  // 5: w_proj
    k_split<<<3072, 256>>>(nullptr, 786432, 32.f, 3);                 // 6: v^T + colsum
    gemm_h<1><<<dim3(16, 8, 96), 256, SM1>>>(nullptr, nullptr);       // 7: qk
    k_mix<<<8192, 256>>>(wre, bre);                                   // 8: mix -> planes
    k_bnfin<<<1, 32>>>(gam, bet);                                     // 9
    gemm_h<2><<<dim3(1, 16, 96), 256, SM2>>>(nullptr, out);           // 10: av + attn out
    gemm_h<3><<<dim3(12, 128, 1), 256, SM3>>>(bp, out);               // 11: proj
}

// round 16
// speedup vs baseline: 1.0025x; 1.0025x over previous
#include <cuda_runtime.h>
#include <cuda_fp16.h>
#include <math.h>
#include <stdint.h>

#define BB 8
#define NSEQ 1024
#define CDIM 768
#define NH 12
#define HD 64
#define SCALE 0.125f
#define BNEPS 1e-5f
#define OUT_OFF (BB*NSEQ*CDIM)
#define NN ((size_t)NSEQ*NSEQ)

// plane sizes (hi plane at [0], lo plane at [OFF])
#define XOFF  (BB*NSEQ*CDIM)      // 6291456
#define WQOFF (3*CDIM*CDIM)       // 1769472
#define WPOFF (CDIM*CDIM)         // 589824
#define QOFF  (BB*NH*NSEQ*HD)     // 6291456
#define VOFF  (BB*NH*HD*NSEQ)     // 6291456
#define GOFF  (BB*NSEQ*CDIM)      // 6291456
#define MXOFF ((size_t)BB*NH*NSEQ*NSEQ)   // 100663296

// ---------------- scratch: merged hi/lo half planes ----------------------------
__device__ __half g_x  [2*XOFF];    // x * 16
__device__ __half g_wq [2*WQOFF];   // w_qkv * 1024
__device__ __half g_wp [2*WPOFF];   // w_proj * 1024
__device__ __half g_q  [2*QOFF];    // q * 32
__device__ __half g_k  [2*QOFF];    // k * 32
__device__ __half g_vts[2*VOFF];    // v^T * 32 [bh][d][m]
__device__ __half g_g  [2*GOFF];    // attn@v [b*N+n][c]
__device__ __half g_mx [2*MXOFF];   // raw mixed attn * 4096 [bh][n][m]
__device__ float  g_vt [VOFF];      // raw v^T
__device__ float  g_vc [BB*NH*HD];  // colsum of v per (bh, d)
__device__ float  g_logits[BB*NH*NSEQ*NSEQ];   // exp(SCALE * q.k)
__device__ float  g_rs[BB*NH*NSEQ];
__device__ double g_s1[NH];
__device__ double g_s2[NH];
__device__ float  g_bna[NH];
__device__ float  g_bnc[NH];

// ---------------- helpers -------------------------------------------------------
__device__ __forceinline__ uint32_t s2u(const void* p){
    uint32_t a;
    asm("{ .reg .u64 t; cvta.to.shared.u64 t, %1; cvt.u32.u64 %0, t; }" : "=r"(a) : "l"(p));
    return a;
}
__device__ __forceinline__ uint2 split2(float x0, float x1, float s){
    x0 *= s; x1 *= s;
    __half h0 = __float2half_rn(x0), h1 = __float2half_rn(x1);
    __half g0 = __float2half_rn(x0 - __half2float(h0));
    __half g1 = __float2half_rn(x1 - __half2float(h1));
    __half2 hh = __halves2half2(h0, h1), ll = __halves2half2(g0, g1);
    uint2 r;
    r.x = *(uint32_t*)&hh; r.y = *(uint32_t*)&ll;
    return r;
}
__device__ __forceinline__ void mma16f(float* c, const uint32_t* a, const uint32_t* b){
    asm volatile("mma.sync.aligned.m16n8k16.row.col.f32.f16.f16.f32 "
        "{%0,%1,%2,%3}, {%4,%5,%6,%7}, {%8,%9}, {%0,%1,%2,%3};"
        : "+f"(c[0]), "+f"(c[1]), "+f"(c[2]), "+f"(c[3])
        : "r"(a[0]), "r"(a[1]), "r"(a[2]), "r"(a[3]), "r"(b[0]), "r"(b[1]));
}
__device__ __forceinline__ void mma16h(uint32_t* c, const uint32_t* a, const uint32_t* b){
    asm volatile("mma.sync.aligned.m16n8k16.row.col.f16.f16.f16.f16 "
        "{%0,%1}, {%2,%3,%4,%5}, {%6,%7}, {%0,%1};"
        : "+r"(c[0]), "+r"(c[1])
        : "r"(a[0]), "r"(a[1]), "r"(a[2]), "r"(a[3]), "r"(b[0]), "r"(b[1]));
}
__device__ __forceinline__ void ldsm4(uint32_t& r0, uint32_t& r1, uint32_t& r2,
                                      uint32_t& r3, uint32_t addr){
    asm volatile("ldmatrix.sync.aligned.m8n8.x4.shared.b16 {%0,%1,%2,%3}, [%4];"
        : "=r"(r0), "=r"(r1), "=r"(r2), "=r"(r3) : "r"(addr));
}
__device__ __forceinline__ void cpa16(uint32_t dst, const void* src){
    asm volatile("cp.async.cg.shared.global [%0], [%1], 16;" :: "r"(dst), "l"(src));
}
#define CPA_COMMIT() asm volatile("cp.async.commit_group;" ::: "memory")
#define USWZ(row, kg) ((row)*64 + (((kg) ^ (((row)>>1)&3)) << 4))

// ---------------- pre-split: fp32 -> hi/lo half planes ---------------------------
// sel==0 additionally zeroes g_rs / g_vc / g_s1 / g_s2 (replaces k_init)
__global__ void k_split(const float* __restrict__ src, int n8, float s, int sel){
    int i = blockIdx.x * blockDim.x + threadIdx.x;
    if (sel == 0) {
        if (i < BB*NH*NSEQ) g_rs[i] = 0.f;
        if (i < BB*NH*HD)   g_vc[i] = 0.f;
        if (i < NH) { g_s1[i] = 0.0; g_s2[i] = 0.0; }
    }
    if (i >= n8) return;
    const float* p = (sel == 3) ? g_vt : src;
    float4 a = *(const float4*)(p + 8*(size_t)i);
    float4 b = *(const float4*)(p + 8*(size_t)i + 4);
    uint2 u0 = split2(a.x, a.y, s), u1 = split2(a.z, a.w, s);
    uint2 u2 = split2(b.x, b.y, s), u3 = split2(b.z, b.w, s);
    __half* dh; size_t off;
    if (sel == 0)      { dh = g_x;   off = XOFF; }
    else if (sel == 1) { dh = g_wq;  off = WQOFF; }
    else if (sel == 2) { dh = g_wp;  off = WPOFF; }
    else               { dh = g_vts; off = VOFF; }
    uint4 vh = {u0.x, u1.x, u2.x, u3.x};
    uint4 vl = {u0.y, u1.y, u2.y, u3.y};
    *(uint4*)(dh + 8*(size_t)i)       = vh;
    *(uint4*)(dh + off + 8*(size_t)i) = vl;
    if (sel == 3) {
        float cs = (a.x+a.y+a.z+a.w) + (b.x+b.y+b.z+b.w);
        atomicAdd(&g_vc[(8*(size_t)i) >> 10], cs);
    }
}

// ---------------- ldmatrix MMA core: one k32 chunk -------------------------------
template<int NT, int MT>
__device__ __forceinline__ void mma_chunk_p(
    uint32_t ah_b, uint32_t alo, uint32_t bh_b, uint32_t blo,
    const int* rba, const int* swa, int kha,
    const int* rbb, const int* swb, int khb,
    float accf[MT][NT][4], uint32_t acch[MT][NT][2])
{
    #pragma unroll
    for (int ks = 0; ks < 2; ks++) {
        uint32_t ah[MT][4], al[MT][4], bh4[NT/2][4], bl4[NT/2][4];
        #pragma unroll
        for (int i = 0; i < MT; i++) {
            int kg = ks*2 + kha;
            uint32_t off = rba[i] + (((uint32_t)(kg ^ swa[i])) << 4);
            ldsm4(ah[i][0], ah[i][1], ah[i][2], ah[i][3], ah_b + off);
            ldsm4(al[i][0], al[i][1], al[i][2], al[i][3], ah_b + alo + off);
        }
        #pragma unroll
        for (int g = 0; g < NT/2; g++) {
            int kg = ks*2 + khb;
            uint32_t off = rbb[g] + (((uint32_t)(kg ^ swb[g])) << 4);
            ldsm4(bh4[g][0], bh4[g][1], bh4[g][2], bh4[g][3], bh_b + off);
            ldsm4(bl4[g][0], bl4[g][1], bl4[g][2], bl4[g][3], bh_b + blo + off);
        }
        #pragma unroll
        for (int g = 0; g < NT/2; g++) {
            #pragma unroll
            for (int jj = 0; jj < 2; jj++) {
                int j = g*2 + jj;
                uint32_t bh2[2] = {bh4[g][jj*2], bh4[g][jj*2+1]};
                uint32_t bl2[2] = {bl4[g][jj*2], bl4[g][jj*2+1]};
                #pragma unroll
                for (int i = 0; i < MT; i++) {
                    mma16f(accf[i][j], ah[i], bh2);
                    mma16h(acch[i][j], al[i], bh2);
                    mma16h(acch[i][j], ah[i], bl2);
                }
            }
        }
    }
}

// ---------------- fp16x3 GEMM ----------------------------------------------------
// MODE 0: qkv  A=g_x   B=g_wq  K=768  BM=128 occ2 pipelined -> q,k planes + raw v^T
// MODE 1: qk   A=g_q   B=g_k   K=64   BM=128 occ3 SINGLE-SHOT -> exp + row sums
// MODE 2: av   A=g_mx  B=g_vts K=1024 BM=64 occ3 pipelined -> g_g + FUSED attn
// MODE 3: proj A=g_g   B=g_wp  K=768  BM=64 occ3 pipelined -> d_out (+bias)
template<int MODE>
__global__ __launch_bounds__(256, (MODE==0) ? 2 : 3) void gemm_h(
    const float* __restrict__ bias, float* __restrict__ pC)
{
    constexpr int BM = (MODE==0 || MODE==1) ? 128 : 64;
    constexpr int BN = 64;
    constexpr int NT = 4, MT = BM / 64;
    constexpr int K   = (MODE==1) ? 64 : (MODE==2) ? 1024 : 768;
    constexpr int NC  = K / 32;
    constexpr int APL = BM * 64;            // bytes per A plane
    constexpr int BPL = BN * 64;            // bytes per B plane
    constexpr int STG = 2*APL + 2*BPL;      // stage size

    extern __shared__ __align__(16) char smem[];

    const int tid  = threadIdx.x;
    const int lane = tid & 31, warp = tid >> 5;
    const int wm = warp >> 1, wn = warp & 1;
    const int gid = lane >> 2, tig = lane & 3;
    const int Mblk = blockIdx.y * BM;
    const int Nblk = blockIdx.x * BN;
    const int bh   = blockIdx.z;
    const uint32_t sb = s2u(smem);

    // per-lane ldmatrix address components
    int rba[MT], swa[MT], rbb[NT/2], swb[NT/2];
    const int rA  = (lane & 7) + ((lane & 8) ? 8 : 0);
    const int kha = (lane >> 4) & 1;
    #pragma unroll
    for (int i = 0; i < MT; i++) {
        int row = wm*(MT*16) + i*16 + rA;
        rba[i] = row*64; swa[i] = (row>>1)&3;
    }
    const int rB  = (lane & 7) + ((lane & 16) ? 8 : 0);
    const int khb = (lane >> 3) & 1;
    #pragma unroll
    for (int g = 0; g < NT/2; g++) {
        int row = wn*32 + g*16 + rB;
        rbb[g] = row*64; swb[g] = (row>>1)&3;
    }

    const __half *Ah_g, *Bh_g;
    constexpr size_t ALO = (MODE==0) ? XOFF : (MODE==1) ? QOFF :
                           (MODE==2) ? MXOFF : GOFF;
    constexpr size_t BLO = (MODE==0) ? WQOFF : (MODE==1) ? QOFF :
                           (MODE==2) ? VOFF : WPOFF;
    if constexpr (MODE == 0)      { Ah_g = g_x; Bh_g = g_wq; }
    else if constexpr (MODE == 1) { size_t o = (size_t)bh*NSEQ*HD;
                                    Ah_g = g_q + o; Bh_g = g_k + o; }
    else if constexpr (MODE == 2) { Ah_g = g_mx + (size_t)bh*NN;
                                    Bh_g = g_vts + (size_t)bh*HD*NSEQ; }
    else                          { Ah_g = g_g; Bh_g = g_wp; }

    // BN affine constants (MODE 2 only)
    float na = 0.f, ncs = 0.f, an = 0.f;
    if constexpr (MODE == 2) {
        int gg = bh % NH;
        na = g_bna[gg]; ncs = g_bnc[gg];
        an = na * (1.f / 4096.f);
    }

    float accf[MT][NT][4] = {};
    uint32_t acch[MT][NT][2] = {};

    {
        const int r0 = tid >> 2, kg = tid & 3;
        auto issue = [&](int ch, int s) {
            uint32_t base = sb + s*STG;
            #pragma unroll
            for (int i = 0; i < BM/64; i++) {
                int r = r0 + i*64;
                uint32_t d = base + USWZ(r, kg);
                const __half* src = Ah_g + (size_t)(Mblk + r)*K + ch*32 + kg*8;
                cpa16(d,       src);
                cpa16(d + APL, src + ALO);
            }
            {
                uint32_t d = base + 2*APL + USWZ(r0, kg);
                const __half* src = Bh_g + (size_t)(Nblk + r0)*K + ch*32 + kg*8;
                cpa16(d,       src);
                cpa16(d + BPL, src + BLO);
            }
            CPA_COMMIT();
        };
        if constexpr (MODE == 1) {
            // ======== single-shot: both K-chunks resident, one barrier ========
            issue(0, 0);
            issue(1, 1);
            asm volatile("cp.async.wait_group 0;" ::: "memory");
            __syncthreads();
            mma_chunk_p<NT, MT>(sb,       APL, sb + 2*APL,       BPL,
                                rba, swa, kha, rbb, swb, khb, accf, acch);
            mma_chunk_p<NT, MT>(sb + STG, APL, sb + STG + 2*APL, BPL,
                                rba, swa, kha, rbb, swb, khb, accf, acch);
        } else {
            // ======== 3-stage cp.async pipeline, one barrier per chunk ========
            issue(0, 0);
            issue(1, 1);
            int s_cur = 0, s_nxt2 = 2;
            for (int ch = 0; ch < NC; ch++) {
                if (ch < NC - 1) {
                    asm volatile("cp.async.wait_group 1;" ::: "memory");
                } else {
                    asm volatile("cp.async.wait_group 0;" ::: "memory");
                }
                __syncthreads();
                if (ch + 2 < NC) issue(ch + 2, s_nxt2);
                uint32_t base = sb + s_cur*STG;
                if constexpr (MODE == 2) {
                    // FUSED attn output: read staged A tile (hi+lo), apply
                    // bna/4096*(hi+lo)+bnc, stream to d_out attn slot.
                    const int rr = tid >> 2;
                    const int kp = tid & 3;
                    uint32_t o0 = base + USWZ(rr, kp);
                    uint4 hv = *(const uint4*)(smem + (o0 - sb));
                    uint4 lv = *(const uint4*)(smem + (o0 - sb) + APL);
                    float* dst = pC + OUT_OFF + (size_t)bh*NN
                               + (size_t)(Mblk + rr)*1024 + ch*32 + kp*8;
                    const uint32_t hw[4] = {hv.x, hv.y, hv.z, hv.w};
                    const uint32_t lw[4] = {lv.x, lv.y, lv.z, lv.w};
                    #pragma unroll
                    for (int q = 0; q < 2; q++) {
                        float4 r;
                        float2 a0 = __half22float2(*(__half2*)&hw[q*2+0]);
                        float2 b0 = __half22float2(*(__half2*)&lw[q*2+0]);
                        float2 a1 = __half22float2(*(__half2*)&hw[q*2+1]);
                        float2 b1 = __half22float2(*(__half2*)&lw[q*2+1]);
                        r.x = fmaf(an, a0.x + b0.x, ncs);
                        r.y = fmaf(an, a0.y + b0.y, ncs);
                        r.z = fmaf(an, a1.x + b1.x, ncs);
                        r.w = fmaf(an, a1.y + b1.y, ncs);
                        __stcs((float4*)(dst + q*4), r);
                    }
                }
                mma_chunk_p<NT, MT>(base, APL, base + 2*APL, BPL,
                                    rba, swa, kha, rbb, swb, khb, accf, acch);
                s_cur = (s_cur == 2) ? 0 : s_cur + 1;
                s_nxt2 = (s_nxt2 == 2) ? 0 : s_nxt2 + 1;
            }
            __syncthreads();
        }
    }

    // ----------------- epilogue -----------------
    // UN: qkv 2^-14 (16*1024); qk 2^-10 (32*32); av 2^-17 (4096*32); proj 2^-10
    constexpr float UN = (MODE==0) ? (1.f/16384.f) : (MODE==2) ? (1.f/131072.f)
                                                               : (1.f/1024.f);
    if constexpr (MODE == 1) {
        #pragma unroll
        for (int i = 0; i < MT; i++) {
            #pragma unroll
            for (int p = 0; p < 2; p++) {
                const int row = Mblk + wm*(MT*16) + i*16 + gid + p*8;
                float rsum = 0.f;
                #pragma unroll
                for (int j = 0; j < NT; j++) {
                    __half2 q = *(__half2*)&acch[i][j][p];
                    float2 cc = __half22float2(q);
                    float v0 = (accf[i][j][p*2+0] + cc.x) * UN;
                    float v1 = (accf[i][j][p*2+1] + cc.y) * UN;
                    float e0 = __expf(SCALE * v0);
                    float e1 = __expf(SCALE * v1);
                    int c0 = Nblk + wn*32 + j*8 + tig*2;
                    __stcs((float2*)(g_logits + (size_t)bh*NN + (size_t)row*NSEQ + c0),
                           make_float2(e0, e1));
                    rsum += e0 + e1;
                }
                rsum += __shfl_xor_sync(0xffffffffu, rsum, 1);
                rsum += __shfl_xor_sync(0xffffffffu, rsum, 2);
                if (tig == 0)
                    atomicAdd(&g_rs[(size_t)bh*NSEQ + row], rsum);
            }
        }
    } else {
        #pragma unroll
        for (int i = 0; i < MT; i++) {
            #pragma unroll
            for (int j = 0; j < NT; j++) {
                __half2 q0 = *(__half2*)&acch[i][j][0];
                __half2 q1 = *(__half2*)&acch[i][j][1];
                float2 c01 = __half22float2(q0);
                float2 c23 = __half22float2(q1);
                float cv[4] = {accf[i][j][0] + c01.x, accf[i][j][1] + c01.y,
                               accf[i][j][2] + c23.x, accf[i][j][3] + c23.y};
                int r0 = Mblk + wm*(MT*16) + i*16 + gid;
                int c0 = Nblk + wn*32 + j*8 + tig*2;
                #pragma unroll
                for (int p = 0; p < 2; p++) {
                    int row = r0 + p*8;
                    float v0 = cv[p*2+0] * UN, v1 = cv[p*2+1] * UN;
                    if constexpr (MODE == 0) {
                        int t3 = c0 / CDIM; int rem = c0 - t3*CDIM;
                        int h = rem >> 6, d = rem & 63;
                        int b = row >> 10, n = row & (NSEQ - 1);
                        v0 += bias[c0]; v1 += bias[c0+1];
                        if (t3 < 2) {
                            uint2 sp = split2(v0, v1, 32.f);
                            size_t idx = ((((size_t)(b*NH+h))*NSEQ + n) << 6) + d;
                            __half* dst = (t3 == 0) ? g_q : g_k;
                            *(uint32_t*)(dst + idx)        = sp.x;
                            *(uint32_t*)(dst + QOFF + idx) = sp.y;
                        } else {
                            size_t base = (((size_t)(b*NH+h))*HD + d)*NSEQ + n;
                            g_vt[base]        = v0;
                            g_vt[base + NSEQ] = v1;
                        }
                    } else if constexpr (MODE == 2) {
                        // out = bna*(mix@v) + bnc*colsum(v)
                        int b = bh / NH, g = bh % NH;
                        float w0 = fmaf(na, v0, ncs * g_vc[bh*HD + c0]);
                        float w1 = fmaf(na, v1, ncs * g_vc[bh*HD + c0 + 1]);
                        uint2 sp = split2(w0, w1, 1.f);
                        size_t idx = ((size_t)(b*NSEQ + row))*CDIM + g*HD + c0;
                        *(uint32_t*)(g_g + idx)        = sp.x;
                        *(uint32_t*)(g_g + GOFF + idx) = sp.y;
                    } else {
                        float2 s = make_float2(v0 + bias[c0], v1 + bias[c0+1]);
                        *(float2*)(pC + (size_t)row*CDIM + c0) = s;
                    }
                }
            }
        }
    }
}

// ---------------- streaming softmax-finish + head mix + BN stats ---------------
// writes raw mixed attn as SPLIT fp16 planes (x4096) into g_mx
__global__ void k_mix(const float* __restrict__ w_re, const float* __restrict__ b_re) {
    __shared__ float wre[NH][NH];
    __shared__ float bre[NH], sinv[NH];
    __shared__ float sm1[NH], sm2[NH];
    const int b = blockIdx.x >> 10;
    const int n = blockIdx.x & 1023;
    const int t = threadIdx.x;               // 256
    const int lane = t & 31;
    if (t < NH*NH) wre[t/NH][t%NH] = w_re[t];
    if (t < NH) {
        bre[t] = b_re[t];
        sinv[t] = 1.0f / g_rs[((size_t)(b*NH + t))*NSEQ + n];
        sm1[t] = 0.f; sm2[t] = 0.f;
    }
    __syncthreads();
    const int m = t << 2;
    float L[NH][4];
    #pragma unroll
    for (int h = 0; h < NH; h++) {
        float4 e = __ldcs((const float4*)(g_logits +
                      (((size_t)(b*NH+h))*NSEQ + n)*NSEQ + m));
        float si = sinv[h];
        L[h][0] = e.x*si; L[h][1] = e.y*si; L[h][2] = e.z*si; L[h][3] = e.w*si;
    }
    #pragma unroll
    for (int g = 0; g < NH; g++) {
        float o0=bre[g], o1=bre[g], o2=bre[g], o3=bre[g];
        #pragma unroll
        for (int h = 0; h < NH; h++) {
            float w = wre[g][h];
            o0 = fmaf(w, L[h][0], o0); o1 = fmaf(w, L[h][1], o1);
            o2 = fmaf(w, L[h][2], o2); o3 = fmaf(w, L[h][3], o3);
        }
        size_t idx = (((size_t)(b*NH+g))*NSEQ + n)*NSEQ + m;
        uint2 u01 = split2(o0, o1, 4096.f);
        uint2 u23 = split2(o2, o3, 4096.f);
        uint2 sh = {u01.x, u23.x};
        uint2 sl = {u01.y, u23.y};
        __stcs((uint2*)(g_mx + idx), sh);
        __stcs((uint2*)(g_mx + MXOFF + idx), sl);
        float a = (o0+o1)+(o2+o3);
        float c = o0*o0+o1*o1+o2*o2+o3*o3;
        #pragma unroll
        for (int o = 16; o; o >>= 1) {
            a += __shfl_xor_sync(0xffffffffu, a, o);
            c += __shfl_xor_sync(0xffffffffu, c, o);
        }
        if (lane == 0) { atomicAdd(&sm1[g], a); atomicAdd(&sm2[g], c); }
    }
    __syncthreads();
    if (t < NH) {
        atomicAdd(&g_s1[t], (double)sm1[t]);
        atomicAdd(&g_s2[t], (double)sm2[t]);
    }
}

// ---------------- BN finalize (double precision) --------------------------------
__global__ void k_bnfin(const float* __restrict__ gamma, const float* __restrict__ beta) {
    int g = threadIdx.x;
    if (g < NH) {
        double cnt = (double)BB * NSEQ * NSEQ;
        double mean = g_s1[g] / cnt;
        double var  = g_s2[g] / cnt - mean * mean;
        float a = (float)((double)gamma[g] / sqrt(var + (double)BNEPS));
        g_bna[g] = a;
        g_bnc[g] = beta[g] - a * (float)mean;
    }
}

// ---------------- launcher --------------------------------------------------------
extern "C" void kernel_launch(void* const* d_in, const int* in_sizes, int n_in,
                              void* d_out, int out_size) {
    const float* x    = (const float*)d_in[0];
    const float* wqkv = (const float*)d_in[1];
    const float* bqkv = (const float*)d_in[2];
    const float* wre  = (const float*)d_in[3];
    const float* bre  = (const float*)d_in[4];
    const float* gam  = (const float*)d_in[5];
    const float* bet  = (const float*)d_in[6];
    const float* wp   = (const float*)d_in[7];
    const float* bp   = (const float*)d_in[8];
    float* out = (float*)d_out;

    const int SM0 = 3 * 24576;   // 73728 (mode 0: BM=128, 3-stage)
    const int SM1 = 2 * 24576;   // 49152 (mode 1: BM=128, single-shot 2 stages)
    const int SM2 = 3 * 16384;   // 49152 (mode 2: BM=64, 3-stage)
    const int SM3 = 3 * 16384;   // 49152 (mode 3: BM=64, 3-stage)
    cudaFuncSetAttribute(gemm_h<0>, cudaFuncAttributeMaxDynamicSharedMemorySize, SM0);
    cudaFuncSetAttribute(gemm_h<1>, cudaFuncAttributeMaxDynamicSharedMemorySize, SM1);
    cudaFuncSetAttribute(gemm_h<2>, cudaFuncAttributeMaxDynamicSharedMemorySize, SM2);
    cudaFuncSetAttribute(gemm_h<3>, cudaFuncAttributeMaxDynamicSharedMemorySize, SM3);

    k_split<<<3072, 256>>>(x,    786432, 16.f,   0);                  // 1: x + inits
    k_split<<<864,  256>>>(wqkv, 221184, 1024.f, 1);                  // 2: w_qkv
    gemm_h<0><<<dim3(36, 64, 1), 256, SM0>>>(bqkv, nullptr);          // 3: qkv
    gemm_h<1><<<dim3(16, 8, 96), 256, SM1>>>(nullptr, nullptr);       // 4: qk (PROFILED)
    k_split<<<288,  256>>>(wp,    73728, 1024.f, 2);                  // 5: w_proj
    k_split<<<3072, 256>>>(nullptr, 786432, 32.f, 3);                 // 6: v^T + colsum
    k_mix<<<8192, 256>>>(wre, bre);                                   // 7: mix -> planes
    k_bnfin<<<1, 32>>>(gam, bet);                                     // 8
    gemm_h<2><<<dim3(1, 16, 96), 256, SM2>>>(nullptr, out);           // 9: av + attn out
    gemm_h<3><<<dim3(12, 128, 1), 256, SM3>>>(bp, out);               // 10: proj
}